// round 16
// baseline (speedup 1.0000x reference)
#include <cuda_runtime.h>
#include <cuda_fp16.h>
#include <cstdint>

// ---------------- problem constants ----------------
#define MROWS 8192            // B*S = 4*2048
#define KDIM  2048            // D_IN
#define NDIM  2048            // D_OUT
#define RANK  16

// ---------------- GEMM tiling ----------------
#define BM 128
#define BN 128
#define BK 64                 // fp16 elems per k-iter (=128B row)
#define KITERS (KDIM / BK)    // 32
#define STAGES 3
#define THREADS 128           // 4 warps

#define A_BYTES (BM * BK * 2)                 // 16384 per stage
#define B_BYTES (BN * BK * 2)                 // 16384 per stage
#define STAGE_BYTES (A_BYTES + B_BYTES)       // 32768
#define SMEM_BYTES (STAGES * STAGE_BYTES + 512)   // 98816

// persistent schedule: 296 CTAs; 3 full tiles each (888) + 272 half-tiles (136 full-equiv)
#define PCTAS 296
#define FULL_TILES 888
#define HALF_ITEMS 272

// prep grid: 1024 weff blocks first, then 16384 x-conversion blocks
#define WEFF_BLOCKS 1024
#define PREPX_BLOCKS ((MROWS * KDIM / 4) / 256)   // 16384

// ---------------- scratch: pre-rounded fp16 operands ----------------
__device__ __half g_x_h[(size_t)MROWS * KDIM];   // 32 MB fp16(x)
__device__ __half g_w_h[(size_t)NDIM * KDIM];    // 8 MB  fp16(W + s*B@A)

// ---------------- PTX helpers (base sm_103 only) ----------------
__device__ __forceinline__ uint32_t smem_u32(const void* p) {
    uint32_t a;
    asm("{ .reg .u64 t; cvta.to.shared.u64 t, %1; cvt.u32.u64 %0, t; }" : "=r"(a) : "l"(p));
    return a;
}

__device__ __forceinline__ void cp_async16(uint32_t saddr, const void* gaddr) {
    asm volatile("cp.async.cg.shared.global [%0], [%1], 16;"
                 :: "r"(saddr), "l"(gaddr) : "memory");
}
#define CP_COMMIT() asm volatile("cp.async.commit_group;" ::: "memory")
#define CP_WAIT_1() asm volatile("cp.async.wait_group 1;" ::: "memory")

__device__ __forceinline__ void ldsm_x4(uint32_t* r, uint32_t addr) {
    asm volatile("ldmatrix.sync.aligned.m8n8.x4.shared.b16 {%0,%1,%2,%3}, [%4];"
                 : "=r"(r[0]), "=r"(r[1]), "=r"(r[2]), "=r"(r[3]) : "r"(addr));
}

__device__ __forceinline__ void mma16n8k16(float* c, const uint32_t* a, const uint32_t* b) {
    asm volatile(
        "mma.sync.aligned.m16n8k16.row.col.f32.f16.f16.f32 "
        "{%0,%1,%2,%3}, {%4,%5,%6,%7}, {%8,%9}, {%0,%1,%2,%3};"
        : "+f"(c[0]), "+f"(c[1]), "+f"(c[2]), "+f"(c[3])
        : "r"(a[0]), "r"(a[1]), "r"(a[2]), "r"(a[3]), "r"(b[0]), "r"(b[1]));
}

// ---------------- fused prep (R15 proven): weff blocks then x conversion ----------------
__global__ void prep_fused(const float4* __restrict__ x,
                           const float* __restrict__ W, const float* __restrict__ A,
                           const float* __restrict__ Bm, const float* __restrict__ scale_p) {
    const int tid = threadIdx.x;      // 256
    if (blockIdx.x < WEFF_BLOCKS) {
        __shared__ float Bs[16 * RANK];   // [o_local][r]
        __shared__ float ss;
        const int o0 = (int)(blockIdx.x >> 3) * 16;
        const int d0 = (int)(blockIdx.x & 7) * 256;

        if (tid < 16 * RANK)
            Bs[tid] = Bm[(size_t)(o0 + (tid >> 4)) * RANK + (tid & 15)];
        if (tid == 0) ss = *scale_p;
        __syncthreads();

        const int d = d0 + tid;
        float ar[RANK];
        {
            float s = ss;
            #pragma unroll
            for (int r = 0; r < RANK; r++)
                ar[r] = s * A[(size_t)r * KDIM + d];
        }
        const float* wcol = W + (size_t)o0 * KDIM + d;
        __half* ocol = g_w_h + (size_t)o0 * KDIM + d;
        #pragma unroll
        for (int ol = 0; ol < 16; ol++) {
            float acc = wcol[(size_t)ol * KDIM];
            const float* brow = Bs + ol * RANK;
            #pragma unroll
            for (int r = 0; r < RANK; r++)
                acc += ar[r] * brow[r];
            ocol[(size_t)ol * KDIM] = __float2half_rn(acc);
        }
    } else {
        size_t i = (size_t)(blockIdx.x - WEFF_BLOCKS) * blockDim.x + tid;
        float4 v = x[i];
        __half2 lo = __floats2half2_rn(v.x, v.y);
        __half2 hi = __floats2half2_rn(v.z, v.w);
        uint2 o;
        o.x = *reinterpret_cast<uint32_t*>(&lo);
        o.y = *reinterpret_cast<uint32_t*>(&hi);
        reinterpret_cast<uint2*>(g_x_h)[i] = o;
    }
}

// ---------------- one output tile (NT=8: 128x128, NT=4: 128x64) ----------------
// Caller must __syncthreads() before calling (smem reuse).
template<int NT>
__device__ __forceinline__ void process_tile(
    int m0, int n0, int tid, int lane, int wid, uint32_t sb, char* smem,
    const __half* __restrict__ x, const __half* __restrict__ w,
    const float* __restrict__ bias, float* __restrict__ out)
{
    float* sBias = reinterpret_cast<float*>(smem + STAGES * STAGE_BYTES);
    const int wm = (wid & 1) * 64;
    const int wn = (wid >> 1) * (NT * 8);       // 64 (full) or 32 (half)

    if (tid < NT * 16) sBias[tid] = bias[n0 + tid];

    const __half* gA = x + (size_t)m0 * KDIM;
    const __half* gB = w + (size_t)n0 * KDIM;

    // quarter q in [0,4): A = 2 passes; B = NT/4 passes (2 full / 1 half)
    auto issue_load_part = [&](int kk, int stage, int q) {
        uint32_t sa = sb + stage * STAGE_BYTES;
        uint32_t sbB = sa + A_BYTES;
        const __half* ga = gA + kk * BK;
        const __half* gb = gB + kk * BK;
        #pragma unroll
        for (int p = q * 2; p < q * 2 + 2; p++) {
            int lin = p * 128 + tid;
            int r = lin >> 3, c = lin & 7;
            uint32_t soff = (uint32_t)(r * 128 + ((c ^ (r & 7)) << 4));
            cp_async16(sa + soff, ga + (size_t)r * KDIM + c * 8);
        }
        #pragma unroll
        for (int p = q * (NT / 4); p < q * (NT / 4) + NT / 4; p++) {
            int lin = p * 128 + tid;
            int r = lin >> 3, c = lin & 7;
            uint32_t soff = (uint32_t)(r * 128 + ((c ^ (r & 7)) << 4));
            cp_async16(sbB + soff, gb + (size_t)r * KDIM + c * 8);
        }
    };
    auto issue_load = [&](int kk, int stage) {
        issue_load_part(kk, stage, 0);
        issue_load_part(kk, stage, 1);
        issue_load_part(kk, stage, 2);
        issue_load_part(kk, stage, 3);
    };

    float acc[4][NT][4];
    #pragma unroll
    for (int mt = 0; mt < 4; mt++)
        #pragma unroll
        for (int nt = 0; nt < NT; nt++)
            #pragma unroll
            for (int j = 0; j < 4; j++) acc[mt][nt][j] = 0.0f;

    issue_load(0, 0); CP_COMMIT();
    issue_load(1, 1); CP_COMMIT();

    const int aRow0 = wm + (lane & 15);
    const int bRow0 = wn + (lane & 7) + ((lane >> 4) << 3);
    const int aHalf = lane >> 4;
    const int bHalf = (lane >> 3) & 1;
    const int sw = lane & 7;

    uint32_t af[2][4][4];
    uint32_t bf[2][NT][2];

    for (int k = 0; k < KITERS; k++) {
        CP_WAIT_1();
        __syncthreads();

        const int knext = k + 2;
        const bool doLoad = (knext < KITERS);
        const int nstage = knext % STAGES;

        const uint32_t aBase = sb + (k % STAGES) * STAGE_BYTES;
        const uint32_t bBase = aBase + A_BYTES;

        auto load_frags = [&](int kt, uint32_t (&afb)[4][4], uint32_t (&bfb)[NT][2]) {
            #pragma unroll
            for (int mt = 0; mt < 4; mt++) {
                int row = aRow0 + mt * 16;
                uint32_t addr = aBase + row * 128 + (uint32_t)(((kt * 2 + aHalf) ^ sw) << 4);
                ldsm_x4(afb[mt], addr);
            }
            #pragma unroll
            for (int np = 0; np < NT / 2; np++) {
                int row = bRow0 + np * 16;
                uint32_t addr = bBase + row * 128 + (uint32_t)(((kt * 2 + bHalf) ^ sw) << 4);
                uint32_t t4[4];
                ldsm_x4(t4, addr);
                bfb[np * 2 + 0][0] = t4[0]; bfb[np * 2 + 0][1] = t4[1];
                bfb[np * 2 + 1][0] = t4[2]; bfb[np * 2 + 1][1] = t4[3];
            }
        };

        load_frags(0, af[0], bf[0]);

        #pragma unroll
        for (int kt = 0; kt < 4; kt++) {
            const int cur = kt & 1;
            if (kt < 3) load_frags(kt + 1, af[cur ^ 1], bf[cur ^ 1]);
            if (doLoad) issue_load_part(knext, nstage, kt);
            #pragma unroll
            for (int mt = 0; mt < 4; mt++)
                #pragma unroll
                for (int nt = 0; nt < NT; nt++)
                    mma16n8k16(acc[mt][nt], af[cur][mt], bf[cur][nt]);
        }
        CP_COMMIT();
    }

    // epilogue: bias add + float2 stores
    #pragma unroll
    for (int mt = 0; mt < 4; mt++) {
        int r0 = m0 + wm + mt * 16 + (lane >> 2);
        #pragma unroll
        for (int nt = 0; nt < NT; nt++) {
            int cl = wn + nt * 8 + (lane & 3) * 2;
            float bx = sBias[cl], by = sBias[cl + 1];
            int c = n0 + cl;
            float2 v0, v1;
            v0.x = acc[mt][nt][0] + bx;
            v0.y = acc[mt][nt][1] + by;
            v1.x = acc[mt][nt][2] + bx;
            v1.y = acc[mt][nt][3] + by;
            *reinterpret_cast<float2*>(out + (size_t)r0 * NDIM + c)       = v0;
            *reinterpret_cast<float2*>(out + (size_t)(r0 + 8) * NDIM + c) = v1;
        }
    }
}

// ---------------- persistent GEMM: 296 CTAs, 3 full tiles + optional half tile ----------------
__global__ void __launch_bounds__(THREADS, 2)
gemm_f16(const __half* __restrict__ x, const __half* __restrict__ w,
         const float* __restrict__ bias, float* __restrict__ out) {
    extern __shared__ char smem[];
    const uint32_t sb = smem_u32(smem);
    const int tid  = threadIdx.x;
    const int lane = tid & 31;
    const int wid  = tid >> 5;

    #pragma unroll
    for (int wave = 0; wave < 3; wave++) {
        int t = (int)blockIdx.x + wave * PCTAS;     // 0..887
        int m0 = (t >> 4) * BM;
        int n0 = (t & 15) * BN;
        __syncthreads();    // smem (sBias/stages) reuse barrier between tiles
        process_tile<8>(m0, n0, tid, lane, wid, sb, smem, x, w, bias, out);
    }
    if (blockIdx.x < HALF_ITEMS) {
        int h = (int)blockIdx.x;
        int t = FULL_TILES + (h >> 1);              // full tile 888..1023
        int m0 = (t >> 4) * BM;
        int n0 = (t & 15) * BN + (h & 1) * 64;
        __syncthreads();
        process_tile<4>(m0, n0, tid, lane, wid, sb, smem, x, w, bias, out);
    }
}

// ---------------- host launch ----------------
extern "C" void kernel_launch(void* const* d_in, const int* in_sizes, int n_in,
                              void* d_out, int out_size) {
    (void)in_sizes; (void)n_in; (void)out_size;
    const float* x     = (const float*)d_in[0];
    const float* W     = (const float*)d_in[1];
    const float* b     = (const float*)d_in[2];
    const float* A     = (const float*)d_in[3];
    const float* Bm    = (const float*)d_in[4];
    const float* scale = (const float*)d_in[5];
    float* out = (float*)d_out;

    void* xh = nullptr;
    void* wh = nullptr;
    cudaGetSymbolAddress(&xh, g_x_h);
    cudaGetSymbolAddress(&wh, g_w_h);

    prep_fused<<<WEFF_BLOCKS + PREPX_BLOCKS, 256>>>((const float4*)x, W, A, Bm, scale);

    cudaFuncSetAttribute(gemm_f16, cudaFuncAttributeMaxDynamicSharedMemorySize, SMEM_BYTES);
    gemm_f16<<<PCTAS, THREADS, SMEM_BYTES>>>((const __half*)xh, (const __half*)wh, b, out);
}

// round 17
// speedup vs baseline: 1.1529x; 1.1529x over previous
#include <cuda_runtime.h>
#include <cuda_fp16.h>
#include <cstdint>

// ---------------- problem constants ----------------
#define MROWS 8192            // B*S = 4*2048
#define KDIM  2048            // D_IN
#define NDIM  2048            // D_OUT
#define RANK  16

// ---------------- GEMM tiling (R9/R15 proven config) ----------------
#define BM 128
#define BN 128
#define BK 64                 // fp16 elems per k-iter (=128B row)
#define KITERS (KDIM / BK)    // 32
#define STAGES 3
#define THREADS 128           // 4 warps: 2(M) x 2(N), warp tile 64x64

#define A_BYTES (BM * BK * 2)                 // 16384 per stage
#define B_BYTES (BN * BK * 2)                 // 16384 per stage
#define STAGE_BYTES (A_BYTES + B_BYTES)       // 32768
#define SMEM_BYTES (STAGES * STAGE_BYTES + 512)   // 98816

// prep grid: 1024 weff blocks first, then 16384 x-conversion blocks
#define WEFF_BLOCKS 1024
#define PREPX_BLOCKS ((MROWS * KDIM / 4) / 256)   // 16384

// ---------------- scratch: pre-rounded fp16 operands ----------------
__device__ __half g_x_h[(size_t)MROWS * KDIM];   // 32 MB fp16(x)
__device__ __half g_w_h[(size_t)NDIM * KDIM];    // 8 MB  fp16(W + s*B@A)

// ---------------- PTX helpers (base sm_103 only) ----------------
__device__ __forceinline__ uint32_t smem_u32(const void* p) {
    uint32_t a;
    asm("{ .reg .u64 t; cvta.to.shared.u64 t, %1; cvt.u32.u64 %0, t; }" : "=r"(a) : "l"(p));
    return a;
}

__device__ __forceinline__ void cp_async16(uint32_t saddr, const void* gaddr) {
    asm volatile("cp.async.cg.shared.global [%0], [%1], 16;"
                 :: "r"(saddr), "l"(gaddr) : "memory");
}
#define CP_COMMIT() asm volatile("cp.async.commit_group;" ::: "memory")
#define CP_WAIT_1() asm volatile("cp.async.wait_group 1;" ::: "memory")

__device__ __forceinline__ void ldsm_x4(uint32_t* r, uint32_t addr) {
    asm volatile("ldmatrix.sync.aligned.m8n8.x4.shared.b16 {%0,%1,%2,%3}, [%4];"
                 : "=r"(r[0]), "=r"(r[1]), "=r"(r[2]), "=r"(r[3]) : "r"(addr));
}

__device__ __forceinline__ void mma16n8k16(float* c, const uint32_t* a, const uint32_t* b) {
    asm volatile(
        "mma.sync.aligned.m16n8k16.row.col.f32.f16.f16.f32 "
        "{%0,%1,%2,%3}, {%4,%5,%6,%7}, {%8,%9}, {%0,%1,%2,%3};"
        : "+f"(c[0]), "+f"(c[1]), "+f"(c[2]), "+f"(c[3])
        : "r"(a[0]), "r"(a[1]), "r"(a[2]), "r"(a[3]), "r"(b[0]), "r"(b[1]));
}

// streaming (evict-first) loads/stores for non-reused data
__device__ __forceinline__ float4 ldcs_f4(const float4* p) {
    float4 v;
    asm volatile("ld.global.cs.v4.f32 {%0,%1,%2,%3}, [%4];"
                 : "=f"(v.x), "=f"(v.y), "=f"(v.z), "=f"(v.w) : "l"(p));
    return v;
}
__device__ __forceinline__ float ldcs_f(const float* p) {
    float v;
    asm volatile("ld.global.cs.f32 %0, [%1];" : "=f"(v) : "l"(p));
    return v;
}
__device__ __forceinline__ void stcs_u2(void* p, uint2 v) {
    asm volatile("st.global.cs.v2.u32 [%0], {%1,%2};" :: "l"(p), "r"(v.x), "r"(v.y) : "memory");
}
__device__ __forceinline__ void stcs_u16(void* p, uint16_t v) {
    asm volatile("st.global.cs.u16 [%0], %1;" :: "l"(p), "h"(v) : "memory");
}

// ---------------- fused prep: weff blocks [0,1024) then x-conversion blocks ----------------
// weff: 16 o x 256 d per block; A slice in regs (reused -> default cache); W/out streamed.
// x:    one float4 -> fp16x4 per thread, pure streaming (ld.cs / st.cs).
__global__ void prep_fused(const float4* __restrict__ x,
                           const float* __restrict__ W, const float* __restrict__ A,
                           const float* __restrict__ Bm, const float* __restrict__ scale_p) {
    const int tid = threadIdx.x;      // 256
    if (blockIdx.x < WEFF_BLOCKS) {
        __shared__ float Bs[16 * RANK];   // [o_local][r]
        __shared__ float ss;
        const int o0 = (int)(blockIdx.x >> 3) * 16;
        const int d0 = (int)(blockIdx.x & 7) * 256;

        if (tid < 16 * RANK)
            Bs[tid] = Bm[(size_t)(o0 + (tid >> 4)) * RANK + (tid & 15)];
        if (tid == 0) ss = *scale_p;
        __syncthreads();

        const int d = d0 + tid;
        float ar[RANK];
        {
            float s = ss;
            #pragma unroll
            for (int r = 0; r < RANK; r++)
                ar[r] = s * A[(size_t)r * KDIM + d];   // reused across blocks: default cache
        }

        const float* wcol = W + (size_t)o0 * KDIM + d;
        __half* ocol = g_w_h + (size_t)o0 * KDIM + d;
        #pragma unroll
        for (int ol = 0; ol < 16; ol++) {
            float acc = ldcs_f(wcol + (size_t)ol * KDIM);   // streamed, MLP 16
            const float* brow = Bs + ol * RANK;
            #pragma unroll
            for (int r = 0; r < RANK; r++)
                acc += ar[r] * brow[r];                     // smem broadcast
            __half hv = __float2half_rn(acc);
            stcs_u16(ocol + (size_t)ol * KDIM, *reinterpret_cast<uint16_t*>(&hv));
        }
    } else {
        size_t i = (size_t)(blockIdx.x - WEFF_BLOCKS) * blockDim.x + tid;
        float4 v = ldcs_f4(x + i);
        __half2 lo = __floats2half2_rn(v.x, v.y);
        __half2 hi = __floats2half2_rn(v.z, v.w);
        uint2 o;
        o.x = *reinterpret_cast<uint32_t*>(&lo);
        o.y = *reinterpret_cast<uint32_t*>(&hi);
        stcs_u2(reinterpret_cast<uint2*>(g_x_h) + i, o);
    }
}

// ---------------- main GEMM: out = x @ W_eff^T + b (fp16 mma.sync; R15 proven) ----------------
__global__ void __launch_bounds__(THREADS, 2)
gemm_f16(const __half* __restrict__ x, const __half* __restrict__ w,
         const float* __restrict__ bias, float* __restrict__ out) {
    extern __shared__ char smem[];
    const uint32_t sb = smem_u32(smem);
    float* sBias = reinterpret_cast<float*>(smem + STAGES * STAGE_BYTES);

    const int tid  = threadIdx.x;
    const int lane = tid & 31;
    const int wid  = tid >> 5;
    const int wm   = (wid & 1) * 64;            // warp M offset
    const int wn   = (wid >> 1) * 64;           // warp N offset
    const int m0   = blockIdx.y * BM;
    const int n0   = blockIdx.x * BN;

    sBias[tid] = bias[n0 + tid];

    // ---- cp.async mapping: 1024 16B-chunks per tile, 8 per thread ----
    // chunk (r, c): smem addr = base + r*128 + ((c ^ (r&7)) << 4)
    const __half* gA = x + (size_t)m0 * KDIM;
    const __half* gB = w + (size_t)n0 * KDIM;

    // issue a 2-pass slice (p0, p0+1) of the full 8-pass tile load
    auto issue_load_part = [&](int kk, int stage, int p0) {
        uint32_t sa = sb + stage * STAGE_BYTES;
        uint32_t sbB = sa + A_BYTES;
        const __half* ga = gA + kk * BK;
        const __half* gb = gB + kk * BK;
        #pragma unroll
        for (int p = p0; p < p0 + 2; p++) {
            int lin = p * 128 + tid;
            int r = lin >> 3;
            int c = lin & 7;
            uint32_t soff = (uint32_t)(r * 128 + ((c ^ (r & 7)) << 4));
            cp_async16(sa + soff, ga + (size_t)r * KDIM + c * 8);
            cp_async16(sbB + soff, gb + (size_t)r * KDIM + c * 8);
        }
    };
    auto issue_load = [&](int kk, int stage) {
        issue_load_part(kk, stage, 0);
        issue_load_part(kk, stage, 2);
        issue_load_part(kk, stage, 4);
        issue_load_part(kk, stage, 6);
    };

    float acc[4][8][4];
    #pragma unroll
    for (int mt = 0; mt < 4; mt++)
        #pragma unroll
        for (int nt = 0; nt < 8; nt++)
            #pragma unroll
            for (int j = 0; j < 4; j++) acc[mt][nt][j] = 0.0f;

    issue_load(0, 0); CP_COMMIT();
    issue_load(1, 1); CP_COMMIT();

    // ldmatrix per-lane addressing (verified layout from round 4):
    // A: row = wm + (lane&15) + mt*16, 16B-chunk = kt*2 + (lane>>4)
    // B: row = wn + (lane&7) + ((lane>>4)<<3) + np*16, chunk = kt*2 + ((lane>>3)&1)
    const int aRow0 = wm + (lane & 15);
    const int bRow0 = wn + (lane & 7) + ((lane >> 4) << 3);
    const int aHalf = lane >> 4;
    const int bHalf = (lane >> 3) & 1;
    const int sw = lane & 7;                   // (row & 7) == lane&7 for both

    // double-buffered fragments
    uint32_t af[2][4][4];
    uint32_t bf[2][8][2];

    for (int k = 0; k < KITERS; k++) {
        CP_WAIT_1();
        __syncthreads();

        const int knext = k + 2;
        const bool doLoad = (knext < KITERS);
        const int nstage = knext % STAGES;

        const uint32_t aBase = sb + (k % STAGES) * STAGE_BYTES;
        const uint32_t bBase = aBase + A_BYTES;

        auto load_frags = [&](int kt, uint32_t (&afb)[4][4], uint32_t (&bfb)[8][2]) {
            #pragma unroll
            for (int mt = 0; mt < 4; mt++) {
                int row = aRow0 + mt * 16;
                uint32_t addr = aBase + row * 128 + (uint32_t)(((kt * 2 + aHalf) ^ sw) << 4);
                ldsm_x4(afb[mt], addr);
            }
            #pragma unroll
            for (int np = 0; np < 4; np++) {
                int row = bRow0 + np * 16;
                uint32_t addr = bBase + row * 128 + (uint32_t)(((kt * 2 + bHalf) ^ sw) << 4);
                uint32_t t4[4];
                ldsm_x4(t4, addr);
                bfb[np * 2 + 0][0] = t4[0]; bfb[np * 2 + 0][1] = t4[1];
                bfb[np * 2 + 1][0] = t4[2]; bfb[np * 2 + 1][1] = t4[3];
            }
        };

        load_frags(0, af[0], bf[0]);

        #pragma unroll
        for (int kt = 0; kt < 4; kt++) {
            const int cur = kt & 1;
            if (kt < 3) load_frags(kt + 1, af[cur ^ 1], bf[cur ^ 1]);   // prefetch next kt
            if (doLoad) issue_load_part(knext, nstage, kt * 2);         // spread cp.async
            #pragma unroll
            for (int mt = 0; mt < 4; mt++)
                #pragma unroll
                for (int nt = 0; nt < 8; nt++)
                    mma16n8k16(acc[mt][nt], af[cur][mt], bf[cur][nt]);
        }
        CP_COMMIT();   // one group per k-iter (possibly empty) keeps accounting fixed
    }

    // epilogue: bias add + float2 stores (registers only; no sync needed)
    #pragma unroll
    for (int mt = 0; mt < 4; mt++) {
        int r0 = m0 + wm + mt * 16 + (lane >> 2);
        #pragma unroll
        for (int nt = 0; nt < 8; nt++) {
            int cl = wn + nt * 8 + (lane & 3) * 2;
            float bx = sBias[cl], by = sBias[cl + 1];
            int c = n0 + cl;
            float2 v0, v1;
            v0.x = acc[mt][nt][0] + bx;
            v0.y = acc[mt][nt][1] + by;
            v1.x = acc[mt][nt][2] + bx;
            v1.y = acc[mt][nt][3] + by;
            *reinterpret_cast<float2*>(out + (size_t)r0 * NDIM + c)       = v0;
            *reinterpret_cast<float2*>(out + (size_t)(r0 + 8) * NDIM + c) = v1;
        }
    }
}

// ---------------- host launch ----------------
extern "C" void kernel_launch(void* const* d_in, const int* in_sizes, int n_in,
                              void* d_out, int out_size) {
    (void)in_sizes; (void)n_in; (void)out_size;
    const float* x     = (const float*)d_in[0];
    const float* W     = (const float*)d_in[1];
    const float* b     = (const float*)d_in[2];
    const float* A     = (const float*)d_in[3];
    const float* Bm    = (const float*)d_in[4];
    const float* scale = (const float*)d_in[5];
    float* out = (float*)d_out;

    void* xh = nullptr;
    void* wh = nullptr;
    cudaGetSymbolAddress(&xh, g_x_h);
    cudaGetSymbolAddress(&wh, g_w_h);

    prep_fused<<<WEFF_BLOCKS + PREPX_BLOCKS, 256>>>((const float4*)x, W, A, Bm, scale);

    cudaFuncSetAttribute(gemm_f16, cudaFuncAttributeMaxDynamicSharedMemorySize, SMEM_BYTES);
    dim3 grid(NDIM / BN, MROWS / BM);   // (16, 64) = 1024 CTAs
    gemm_f16<<<grid, THREADS, SMEM_BYTES>>>((const __half*)xh, (const __half*)wh, b, out);
}